// round 1
// baseline (speedup 1.0000x reference)
#include <cuda_runtime.h>
#include <cuda_bf16.h>
#include <math.h>

// ---------------- Problem constants ----------------
#define BB 2
#define LL 1024
#define DM 1024
#define DI 2048            // d_inner
#define DS 16              // d_state
#define DC 4               // d_conv
#define DR 64              // dt_rank
#define XZ_W (2*DI)        // 4096
#define XDBL_W (DR + 2*DS) // 96
#define MROWS (BB*LL)      // 2048

// ---------------- Scratch (device globals; no allocation allowed) ----------------
__device__ float g_xz[BB*LL*XZ_W];     // [B,L,4096]
__device__ float g_u [BB*LL*DI];       // [B,L,2048]
__device__ float g_xdbl[BB*LL*XDBL_W]; // [B,L,96]
__device__ float g_dt[BB*LL*DI];       // [B,L,2048]
__device__ float g_y [BB*LL*DI];       // [B,L,2048]
__device__ float g_h [BB*LL*DM];       // layer-1 output

// ---------------- Generic NT SGEMM: C[m,n] = sum_k A[m*lda+k] * W[n*K+k] ----------------
// EPI: 0 = none, 1 = softplus(c + bias[n]), 2 = c + res[m*N+n]
template <int EPI>
__global__ void sgemm_nt(const float* __restrict__ A, int lda,
                         const float* __restrict__ W,
                         float* __restrict__ C,
                         int M, int N, int K,
                         const float* __restrict__ bias,
                         const float* __restrict__ res)
{
    const int BM = 128, BN = 128, BK = 8;
    __shared__ float As[BK][BM];
    __shared__ float Bs[BK][BN];

    const int tid = threadIdx.x;              // 256 threads
    const int tx  = tid & 15;                  // n sub-tile
    const int ty  = tid >> 4;                  // m sub-tile
    const int by  = blockIdx.y;                // m block
    const int bx  = blockIdx.x;                // n block

    const int arow = tid >> 1;                 // 0..127
    const int acol = (tid & 1) * 4;            // 0 or 4
    const int brow = arow;
    const int bcol = acol;

    const float* Ap = A + (size_t)(by * BM) * lda;
    const float* Wp = W + (size_t)(bx * BN) * K;

    float acc[8][8];
#pragma unroll
    for (int i = 0; i < 8; ++i)
#pragma unroll
        for (int j = 0; j < 8; ++j) acc[i][j] = 0.f;

    for (int k0 = 0; k0 < K; k0 += BK) {
        // load A tile (M assumed multiple of 128, K multiple of 8)
        float4 av = *(const float4*)(Ap + (size_t)arow * lda + k0 + acol);
        As[acol+0][arow] = av.x; As[acol+1][arow] = av.y;
        As[acol+2][arow] = av.z; As[acol+3][arow] = av.w;

        float4 bv = make_float4(0.f, 0.f, 0.f, 0.f);
        int gn = bx * BN + brow;
        if (gn < N) bv = *(const float4*)(Wp + (size_t)brow * K + k0 + bcol);
        Bs[bcol+0][brow] = bv.x; Bs[bcol+1][brow] = bv.y;
        Bs[bcol+2][brow] = bv.z; Bs[bcol+3][brow] = bv.w;

        __syncthreads();
#pragma unroll
        for (int kk = 0; kk < BK; ++kk) {
            float a[8], b[8];
#pragma unroll
            for (int i = 0; i < 8; ++i) a[i] = As[kk][ty * 8 + i];
#pragma unroll
            for (int j = 0; j < 8; ++j) b[j] = Bs[kk][tx * 8 + j];
#pragma unroll
            for (int i = 0; i < 8; ++i)
#pragma unroll
                for (int j = 0; j < 8; ++j) acc[i][j] += a[i] * b[j];
        }
        __syncthreads();
    }

#pragma unroll
    for (int i = 0; i < 8; ++i) {
        int m = by * BM + ty * 8 + i;
#pragma unroll
        for (int j = 0; j < 8; ++j) {
            int n = bx * BN + tx * 8 + j;
            if (n < N) {
                float c = acc[i][j];
                if (EPI == 1) {
                    float v = c + bias[n];
                    c = (v > 20.f) ? v : log1pf(__expf(v));
                } else if (EPI == 2) {
                    c += res[(size_t)m * N + n];
                }
                C[(size_t)m * N + n] = c;
            }
        }
    }
}

// ---------------- Depthwise causal conv1d (width 4) + bias + SiLU ----------------
// reads u-part of g_xz (cols [0,DI)), writes g_u
__global__ void conv_silu_kernel(const float* __restrict__ xz,
                                 const float* __restrict__ cw,
                                 const float* __restrict__ cb,
                                 float* __restrict__ u)
{
    int idx = blockIdx.x * blockDim.x + threadIdx.x;   // over B*L*DI
    if (idx >= BB * LL * DI) return;
    int d  = idx & (DI - 1);
    int bl = idx >> 11;           // /DI
    int l  = bl & (LL - 1);
    int b  = bl >> 10;            // /LL

    float w0 = cw[d * 4 + 0], w1 = cw[d * 4 + 1];
    float w2 = cw[d * 4 + 2], w3 = cw[d * 4 + 3];
    float acc = cb[d];
    const float* base = xz + ((size_t)b * LL) * XZ_W + d;
    if (l - 3 >= 0) acc += base[(size_t)(l - 3) * XZ_W] * w0;
    if (l - 2 >= 0) acc += base[(size_t)(l - 2) * XZ_W] * w1;
    if (l - 1 >= 0) acc += base[(size_t)(l - 1) * XZ_W] * w2;
    acc += base[(size_t)l * XZ_W] * w3;
    float s = acc / (1.f + __expf(-acc));   // SiLU
    u[idx] = s;
}

// ---------------- Selective scan ----------------
// 4 lanes per (b,d) row, 4 states per lane. 128 threads = 32 rows per block.
// grid = B * (DI/32) = 128 blocks.
#define TCH 64
__global__ void scan_kernel(const float* __restrict__ dt,
                            const float* __restrict__ u,
                            const float* __restrict__ xdbl,
                            const float* __restrict__ A_log,
                            const float* __restrict__ Dvec,
                            const float* __restrict__ xz,
                            float* __restrict__ y)
{
    __shared__ float sB[TCH][DS];
    __shared__ float sC[TCH][DS];

    const int q  = threadIdx.x & 3;     // state quad
    const int dl = threadIdx.x >> 2;    // local row
    const int b  = blockIdx.x >> 6;     // / (DI/32)
    const int d  = ((blockIdx.x & 63) << 5) + dl;

    float Av[4];
#pragma unroll
    for (int i = 0; i < 4; ++i)
        Av[i] = -__expf(A_log[(size_t)d * DS + q * 4 + i]);
    const float Dv = Dvec[d];

    float h0 = 0.f, h1 = 0.f, h2 = 0.f, h3 = 0.f;

    for (int t0 = 0; t0 < LL; t0 += TCH) {
        __syncthreads();
        for (int i = threadIdx.x; i < TCH * DS; i += blockDim.x) {
            int tt = i >> 4, n = i & 15;
            size_t row = ((size_t)b * LL + t0 + tt) * XDBL_W;
            sB[tt][n] = xdbl[row + DR + n];
            sC[tt][n] = xdbl[row + DR + DS + n];
        }
        __syncthreads();

#pragma unroll 4
        for (int tt = 0; tt < TCH; ++tt) {
            int t = t0 + tt;
            size_t off = ((size_t)b * LL + t) * DI + d;
            float dtv = dt[off];
            float uv  = u[off];
            float dtu = dtv * uv;

            float ys;
            {
                float dA0 = __expf(dtv * Av[0]);
                float dA1 = __expf(dtv * Av[1]);
                float dA2 = __expf(dtv * Av[2]);
                float dA3 = __expf(dtv * Av[3]);
                h0 = dA0 * h0 + dtu * sB[tt][q * 4 + 0];
                h1 = dA1 * h1 + dtu * sB[tt][q * 4 + 1];
                h2 = dA2 * h2 + dtu * sB[tt][q * 4 + 2];
                h3 = dA3 * h3 + dtu * sB[tt][q * 4 + 3];
                ys = h0 * sC[tt][q * 4 + 0] + h1 * sC[tt][q * 4 + 1]
                   + h2 * sC[tt][q * 4 + 2] + h3 * sC[tt][q * 4 + 3];
            }
            ys += __shfl_xor_sync(0xffffffff, ys, 1);
            ys += __shfl_xor_sync(0xffffffff, ys, 2);

            if (q == 0) {
                float zv = xz[((size_t)b * LL + t) * XZ_W + DI + d];
                float sz = zv / (1.f + __expf(-zv));
                y[off] = (ys + uv * Dv) * sz;
            }
        }
    }
}

// ---------------- Host launcher ----------------
extern "C" void kernel_launch(void* const* d_in, const int* in_sizes, int n_in,
                              void* d_out, int out_size)
{
    const float* x      = (const float*)d_in[0];
    const float* W_in   = (const float*)d_in[1];
    const float* conv_w = (const float*)d_in[2];
    const float* conv_b = (const float*)d_in[3];
    const float* W_x    = (const float*)d_in[4];
    const float* W_dt   = (const float*)d_in[5];
    const float* b_dt   = (const float*)d_in[6];
    const float* A_log  = (const float*)d_in[7];
    const float* Dvec   = (const float*)d_in[8];
    const float* W_out  = (const float*)d_in[9];
    float* out = (float*)d_out;

    float *xz, *u, *xdbl, *dt, *y, *hbuf;
    cudaGetSymbolAddress((void**)&xz,   g_xz);
    cudaGetSymbolAddress((void**)&u,    g_u);
    cudaGetSymbolAddress((void**)&xdbl, g_xdbl);
    cudaGetSymbolAddress((void**)&dt,   g_dt);
    cudaGetSymbolAddress((void**)&y,    g_y);
    cudaGetSymbolAddress((void**)&hbuf, g_h);

    for (int layer = 0; layer < 2; ++layer) {
        const float* in = (layer == 0) ? x : hbuf;
        const float* W_in_l   = W_in   + (size_t)layer * XZ_W * DM;
        const float* conv_w_l = conv_w + (size_t)layer * DI * DC;
        const float* conv_b_l = conv_b + (size_t)layer * DI;
        const float* W_x_l    = W_x    + (size_t)layer * XDBL_W * DI;
        const float* W_dt_l   = W_dt   + (size_t)layer * DI * DR;
        const float* b_dt_l   = b_dt   + (size_t)layer * DI;
        const float* A_log_l  = A_log  + (size_t)layer * DI * DS;
        const float* D_l      = Dvec   + (size_t)layer * DI;
        const float* W_out_l  = W_out  + (size_t)layer * DM * DI;

        // 1) xz = in @ W_in^T : [2048, 4096], K=1024
        sgemm_nt<0><<<dim3(XZ_W / 128, MROWS / 128), 256>>>(
            in, DM, W_in_l, xz, MROWS, XZ_W, DM, nullptr, nullptr);

        // 2) u = silu(causal_conv(xz[:, :DI]))
        conv_silu_kernel<<<(BB * LL * DI) / 256, 256>>>(xz, conv_w_l, conv_b_l, u);

        // 3) x_dbl = u @ W_x^T : [2048, 96], K=2048
        sgemm_nt<0><<<dim3((XDBL_W + 127) / 128, MROWS / 128), 256>>>(
            u, DI, W_x_l, xdbl, MROWS, XDBL_W, DI, nullptr, nullptr);

        // 4) dt = softplus(x_dbl[:, :64] @ W_dt^T + b_dt) : [2048, 2048], K=64
        sgemm_nt<1><<<dim3(DI / 128, MROWS / 128), 256>>>(
            xdbl, XDBL_W, W_dt_l, dt, MROWS, DI, DR, b_dt_l, nullptr);

        // 5) selective scan (+ *silu(z), + u*D)
        scan_kernel<<<BB * (DI / 32), 128>>>(dt, u, xdbl, A_log_l, D_l, xz, y);

        // 6) out = y @ W_out^T : [2048, 1024], K=2048 (+ residual x on last layer)
        if (layer == 0) {
            sgemm_nt<0><<<dim3(DM / 128, MROWS / 128), 256>>>(
                y, DI, W_out_l, hbuf, MROWS, DM, DI, nullptr, nullptr);
        } else {
            sgemm_nt<2><<<dim3(DM / 128, MROWS / 128), 256>>>(
                y, DI, W_out_l, out, MROWS, DM, DI, nullptr, x);
        }
    }
}

// round 3
// speedup vs baseline: 1.9444x; 1.9444x over previous
#include <cuda_runtime.h>
#include <cuda_bf16.h>
#include <mma.h>
#include <cstdint>
#include <math.h>

using namespace nvcuda;

// ---------------- Problem constants ----------------
#define BB 2
#define LL 1024
#define DM 1024
#define DI 2048            // d_inner
#define DS 16              // d_state
#define DC 4               // d_conv
#define DR 64              // dt_rank
#define XZ_W (2*DI)        // 4096
#define XDBL_W (DR + 2*DS) // 96
#define MROWS (BB*LL)      // 2048

// ---------------- Scratch (device globals; no allocation allowed) ----------------
__device__ float g_xz  [MROWS*XZ_W];    // fp32 [2048,4096]
__device__ float g_u   [MROWS*DI];
__device__ float g_xdbl[MROWS*XDBL_W];
__device__ float g_dt  [MROWS*DI];
__device__ __nv_bfloat16 g_xb   [MROWS*DM];
__device__ __nv_bfloat16 g_hb   [MROWS*DM];
__device__ __nv_bfloat16 g_ub   [MROWS*DI];
__device__ __nv_bfloat16 g_yb   [MROWS*DI];
__device__ __nv_bfloat16 g_xdblb[MROWS*XDBL_W];
__device__ __nv_bfloat16 g_Wib  [2*XZ_W*DM];
__device__ __nv_bfloat16 g_Wxb  [2*XDBL_W*DI];
__device__ __nv_bfloat16 g_Wdtb [2*DI*DR];
__device__ __nv_bfloat16 g_Wob  [2*DM*DI];

// ---------------- helpers ----------------
__device__ __forceinline__ uint32_t smem_u32(const void* p) {
    uint32_t a;
    asm("{ .reg .u64 t; cvta.to.shared.u64 t, %1; cvt.u32.u64 %0, t; }" : "=r"(a) : "l"(p));
    return a;
}
__device__ __forceinline__ void cp16(uint32_t s, const void* g) {
    asm volatile("cp.async.cg.shared.global [%0], [%1], 16;" :: "r"(s), "l"(g));
}
#define CP_COMMIT()  asm volatile("cp.async.commit_group;" ::: "memory")
#define CP_WAIT(n)   asm volatile("cp.async.wait_group %0;" :: "n"(n) : "memory")

// ---------------- WMMA bf16 NT GEMM ----------------
// C[m,n] = sum_k A[m*lda+k] * W[n*K+k]   (A, W bf16 K-major)
// CTA tile 128x128, BK=32, 8 warps: warp (mw = wid&3 -> 32 rows, nw = wid>>2 -> 64 cols)
// EPI: 0=fp32, 1=softplus(c+bias[n]) fp32, 2=c+res fp32, 3=bf16 only, 4=fp32+bf16
#define LDT 40              // smem row stride, bf16 elements (80B)
#define STAGE_BYTES 20480   // A (10240) + B (10240)
#define EPI_LD 72           // epilogue float row stride

template <int EPI>
__global__ void __launch_bounds__(256)
gemm_wmma(const __nv_bfloat16* __restrict__ A, int lda,
          const __nv_bfloat16* __restrict__ W,
          float* __restrict__ Cf, __nv_bfloat16* __restrict__ Cb,
          int N, int ldc, int K,
          const float* __restrict__ bias, const float* __restrict__ res)
{
    extern __shared__ __align__(16) char smem[];   // 2*STAGE_BYTES = 40960

    const int tid = threadIdx.x;
    const int wid = tid >> 5;
    const int mw  = wid & 3;        // m-warp: rows [mw*32, mw*32+32)
    const int nw  = wid >> 2;       // n-warp: cols [nw*64, nw*64+64)
    const int bx  = blockIdx.x, by = blockIdx.y;

    const uint32_t sbase = smem_u32(smem);
    const __nv_bfloat16* Ap = A + (size_t)(by * 128) * lda;
    const __nv_bfloat16* Wp = W + (size_t)(bx * 128) * K;

    const int nk = K >> 5;

    // per-thread load coords: 2 chunks of 16B for A, 2 for B per stage
    const int c0 = tid * 2;         // chunk ids c0, c0+1 in [0,512)

    auto load_stage = [&](int kt, int st) {
        const int k0 = kt * 32;
        uint32_t sa = sbase + st * STAGE_BYTES;
        uint32_t sb = sa + 10240;
#pragma unroll
        for (int j = 0; j < 2; ++j) {
            int c   = c0 + j;
            int row = c >> 2, col = c & 3;
            cp16(sa + row * 80 + col * 16, Ap + (size_t)row * lda + k0 + col * 8);
            int gn = bx * 128 + row;
            if (gn < N)
                cp16(sb + row * 80 + col * 16, Wp + (size_t)row * K + k0 + col * 8);
        }
        CP_COMMIT();
    };

    wmma::fragment<wmma::accumulator, 16, 16, 16, float> acc[2][4];
#pragma unroll
    for (int i = 0; i < 2; ++i)
#pragma unroll
        for (int j = 0; j < 4; ++j) wmma::fill_fragment(acc[i][j], 0.f);

    load_stage(0, 0);

    for (int kt = 0; kt < nk; ++kt) {
        if (kt + 1 < nk) { load_stage(kt + 1, (kt + 1) & 1); CP_WAIT(1); }
        else             { CP_WAIT(0); }
        __syncthreads();

        const __nv_bfloat16* sA = (const __nv_bfloat16*)(smem + (kt & 1) * STAGE_BYTES);
        const __nv_bfloat16* sB = sA + 10240 / 2;
#pragma unroll
        for (int ks = 0; ks < 2; ++ks) {
            wmma::fragment<wmma::matrix_a, 16, 16, 16, __nv_bfloat16, wmma::row_major> af[2];
            wmma::fragment<wmma::matrix_b, 16, 16, 16, __nv_bfloat16, wmma::col_major> bfr[4];
#pragma unroll
            for (int i = 0; i < 2; ++i)
                wmma::load_matrix_sync(af[i], sA + (mw * 32 + i * 16) * LDT + ks * 16, LDT);
#pragma unroll
            for (int j = 0; j < 4; ++j)
                wmma::load_matrix_sync(bfr[j], sB + (nw * 64 + j * 16) * LDT + ks * 16, LDT);
#pragma unroll
            for (int i = 0; i < 2; ++i)
#pragma unroll
                for (int j = 0; j < 4; ++j)
                    wmma::mma_sync(acc[i][j], af[i], bfr[j], acc[i][j]);
        }
        __syncthreads();
    }

    // ---------------- epilogue: acc -> SMEM (fp32) -> coalesced GMEM ----------------
    float* sEpi = (float*)smem;   // [128][EPI_LD], aliases stage buffers
#pragma unroll
    for (int c = 0; c < 2; ++c) {
        if (nw == c) {
#pragma unroll
            for (int i = 0; i < 2; ++i)
#pragma unroll
                for (int j = 0; j < 4; ++j)
                    wmma::store_matrix_sync(sEpi + (mw * 32 + i * 16) * EPI_LD + j * 16,
                                            acc[i][j], EPI_LD, wmma::mem_row_major);
        }
        __syncthreads();

        int nn = tid & 63, r0 = tid >> 6;
        int n = bx * 128 + c * 64 + nn;
        if (n < N) {
            float bv = (EPI == 1) ? bias[n] : 0.f;
#pragma unroll 4
            for (int rr = r0; rr < 128; rr += 4) {
                int m = by * 128 + rr;
                float v = sEpi[rr * EPI_LD + nn];
                if (EPI == 1) {
                    float t = v + bv;
                    v = (t > 20.f) ? t : log1pf(__expf(t));
                    Cf[(size_t)m * ldc + n] = v;
                } else if (EPI == 2) {
                    Cf[(size_t)m * ldc + n] = v + res[(size_t)m * ldc + n];
                } else if (EPI == 3) {
                    Cb[(size_t)m * ldc + n] = __float2bfloat16(v);
                } else if (EPI == 4) {
                    Cf[(size_t)m * ldc + n] = v;
                    Cb[(size_t)m * ldc + n] = __float2bfloat16(v);
                } else {
                    Cf[(size_t)m * ldc + n] = v;
                }
            }
        }
        __syncthreads();
    }
}

// ---------------- fp32 -> bf16 convert ----------------
__global__ void cvt_kernel(const float* __restrict__ in, __nv_bfloat16* __restrict__ out, int n)
{
    int i = (blockIdx.x * blockDim.x + threadIdx.x) * 4;
    if (i + 3 < n) {
        float4 v = *(const float4*)(in + i);
        *(__nv_bfloat162*)(out + i)     = __floats2bfloat162_rn(v.x, v.y);
        *(__nv_bfloat162*)(out + i + 2) = __floats2bfloat162_rn(v.z, v.w);
    }
}

// ---------------- Depthwise causal conv1d (width 4) + bias + SiLU ----------------
__global__ void conv_silu_kernel(const float* __restrict__ xz,
                                 const float* __restrict__ cw,
                                 const float* __restrict__ cb,
                                 float* __restrict__ u,
                                 __nv_bfloat16* __restrict__ ub)
{
    int idx = blockIdx.x * blockDim.x + threadIdx.x;
    if (idx >= BB * LL * DI) return;
    int d  = idx & (DI - 1);
    int bl = idx >> 11;
    int l  = bl & (LL - 1);
    int b  = bl >> 10;

    float w0 = cw[d * 4 + 0], w1 = cw[d * 4 + 1];
    float w2 = cw[d * 4 + 2], w3 = cw[d * 4 + 3];
    float acc = cb[d];
    const float* base = xz + ((size_t)b * LL) * XZ_W + d;
    if (l - 3 >= 0) acc += base[(size_t)(l - 3) * XZ_W] * w0;
    if (l - 2 >= 0) acc += base[(size_t)(l - 2) * XZ_W] * w1;
    if (l - 1 >= 0) acc += base[(size_t)(l - 1) * XZ_W] * w2;
    acc += base[(size_t)l * XZ_W] * w3;
    float s = acc / (1.f + __expf(-acc));
    u[idx]  = s;
    ub[idx] = __float2bfloat16(s);
}

// ---------------- Selective scan ----------------
#define TCH 64
__global__ void scan_kernel(const float* __restrict__ dt,
                            const float* __restrict__ u,
                            const float* __restrict__ xdbl,
                            const float* __restrict__ A_log,
                            const float* __restrict__ Dvec,
                            const float* __restrict__ xz,
                            __nv_bfloat16* __restrict__ yb)
{
    __shared__ float sB[TCH][DS];
    __shared__ float sC[TCH][DS];

    const int q  = threadIdx.x & 3;
    const int dl = threadIdx.x >> 2;
    const int b  = blockIdx.x >> 6;
    const int d  = ((blockIdx.x & 63) << 5) + dl;

    float Av[4];
#pragma unroll
    for (int i = 0; i < 4; ++i)
        Av[i] = -__expf(A_log[(size_t)d * DS + q * 4 + i]);
    const float Dv = Dvec[d];

    float h0 = 0.f, h1 = 0.f, h2 = 0.f, h3 = 0.f;

    for (int t0 = 0; t0 < LL; t0 += TCH) {
        __syncthreads();
        for (int i = threadIdx.x; i < TCH * DS; i += blockDim.x) {
            int tt = i >> 4, n = i & 15;
            size_t row = ((size_t)b * LL + t0 + tt) * XDBL_W;
            sB[tt][n] = xdbl[row + DR + n];
            sC[tt][n] = xdbl[row + DR + DS + n];
        }
        __syncthreads();

#pragma unroll 4
        for (int tt = 0; tt < TCH; ++tt) {
            int t = t0 + tt;
            size_t off = ((size_t)b * LL + t) * DI + d;
            float dtv = dt[off];
            float uv  = u[off];
            float dtu = dtv * uv;

            float dA0 = __expf(dtv * Av[0]);
            float dA1 = __expf(dtv * Av[1]);
            float dA2 = __expf(dtv * Av[2]);
            float dA3 = __expf(dtv * Av[3]);
            h0 = dA0 * h0 + dtu * sB[tt][q * 4 + 0];
            h1 = dA1 * h1 + dtu * sB[tt][q * 4 + 1];
            h2 = dA2 * h2 + dtu * sB[tt][q * 4 + 2];
            h3 = dA3 * h3 + dtu * sB[tt][q * 4 + 3];
            float ys = h0 * sC[tt][q * 4 + 0] + h1 * sC[tt][q * 4 + 1]
                     + h2 * sC[tt][q * 4 + 2] + h3 * sC[tt][q * 4 + 3];

            ys += __shfl_xor_sync(0xffffffff, ys, 1);
            ys += __shfl_xor_sync(0xffffffff, ys, 2);

            if (q == 0) {
                float zv = xz[((size_t)b * LL + t) * XZ_W + DI + d];
                float sz = zv / (1.f + __expf(-zv));
                yb[off] = __float2bfloat16((ys + uv * Dv) * sz);
            }
        }
    }
}

// ---------------- Host launcher ----------------
extern "C" void kernel_launch(void* const* d_in, const int* in_sizes, int n_in,
                              void* d_out, int out_size)
{
    const float* x      = (const float*)d_in[0];
    const float* W_in   = (const float*)d_in[1];
    const float* conv_w = (const float*)d_in[2];
    const float* conv_b = (const float*)d_in[3];
    const float* W_x    = (const float*)d_in[4];
    const float* W_dt   = (const float*)d_in[5];
    const float* b_dt   = (const float*)d_in[6];
    const float* A_log  = (const float*)d_in[7];
    const float* Dvec   = (const float*)d_in[8];
    const float* W_out  = (const float*)d_in[9];
    float* out = (float*)d_out;

    float *xz, *u, *xdbl, *dt;
    __nv_bfloat16 *xb, *hb, *ub, *yb, *xdblb, *Wib, *Wxb, *Wdtb, *Wob;
    cudaGetSymbolAddress((void**)&xz,    g_xz);
    cudaGetSymbolAddress((void**)&u,     g_u);
    cudaGetSymbolAddress((void**)&xdbl,  g_xdbl);
    cudaGetSymbolAddress((void**)&dt,    g_dt);
    cudaGetSymbolAddress((void**)&xb,    g_xb);
    cudaGetSymbolAddress((void**)&hb,    g_hb);
    cudaGetSymbolAddress((void**)&ub,    g_ub);
    cudaGetSymbolAddress((void**)&yb,    g_yb);
    cudaGetSymbolAddress((void**)&xdblb, g_xdblb);
    cudaGetSymbolAddress((void**)&Wib,   g_Wib);
    cudaGetSymbolAddress((void**)&Wxb,   g_Wxb);
    cudaGetSymbolAddress((void**)&Wdtb,  g_Wdtb);
    cudaGetSymbolAddress((void**)&Wob,   g_Wob);

    const int SMEM = 2 * STAGE_BYTES;   // 40960

    // convert weights + x to bf16
    auto cvt = [&](const float* src, __nv_bfloat16* dst, int n) {
        cvt_kernel<<<(n / 4 + 255) / 256, 256>>>(src, dst, n);
    };
    cvt(x,     xb,   MROWS * DM);
    cvt(W_in,  Wib,  2 * XZ_W * DM);
    cvt(W_x,   Wxb,  2 * XDBL_W * DI);
    cvt(W_dt,  Wdtb, 2 * DI * DR);
    cvt(W_out, Wob,  2 * DM * DI);

    for (int layer = 0; layer < 2; ++layer) {
        const __nv_bfloat16* in_b   = (layer == 0) ? xb : hb;
        const __nv_bfloat16* Wib_l  = Wib  + (size_t)layer * XZ_W * DM;
        const __nv_bfloat16* Wxb_l  = Wxb  + (size_t)layer * XDBL_W * DI;
        const __nv_bfloat16* Wdtb_l = Wdtb + (size_t)layer * DI * DR;
        const __nv_bfloat16* Wob_l  = Wob  + (size_t)layer * DM * DI;
        const float* conv_w_l = conv_w + (size_t)layer * DI * DC;
        const float* conv_b_l = conv_b + (size_t)layer * DI;
        const float* b_dt_l   = b_dt   + (size_t)layer * DI;
        const float* A_log_l  = A_log  + (size_t)layer * DI * DS;
        const float* D_l      = Dvec   + (size_t)layer * DI;

        // 1) xz = in @ W_in^T : M=2048, N=4096, K=1024
        gemm_wmma<0><<<dim3(XZ_W / 128, MROWS / 128), 256, SMEM>>>(
            in_b, DM, Wib_l, xz, nullptr, XZ_W, XZ_W, DM, nullptr, nullptr);

        // 2) u = silu(causal_conv(xz[:, :DI]))  (fp32 + bf16)
        conv_silu_kernel<<<(BB * LL * DI) / 256, 256>>>(xz, conv_w_l, conv_b_l, u, ub);

        // 3) x_dbl = u @ W_x^T : N=96, K=2048  (fp32 + bf16)
        gemm_wmma<4><<<dim3(1, MROWS / 128), 256, SMEM>>>(
            ub, DI, Wxb_l, xdbl, xdblb, XDBL_W, XDBL_W, DI, nullptr, nullptr);

        // 4) dt = softplus(x_dbl[:, :64] @ W_dt^T + b_dt) : N=2048, K=64
        gemm_wmma<1><<<dim3(DI / 128, MROWS / 128), 256, SMEM>>>(
            xdblb, XDBL_W, Wdtb_l, dt, nullptr, DI, DI, DR, b_dt_l, nullptr);

        // 5) selective scan (+ *silu(z), + u*D) -> y bf16
        scan_kernel<<<BB * (DI / 32), 128>>>(dt, u, xdbl, A_log_l, D_l, xz, yb);

        // 6) out = y @ W_out^T : N=1024, K=2048
        if (layer == 0) {
            gemm_wmma<3><<<dim3(DM / 128, MROWS / 128), 256, SMEM>>>(
                yb, DI, Wob_l, nullptr, hb, DM, DM, DI, nullptr, nullptr);
        } else {
            gemm_wmma<2><<<dim3(DM / 128, MROWS / 128), 256, SMEM>>>(
                yb, DI, Wob_l, out, nullptr, DM, DM, DI, nullptr, x);
        }
    }
}

// round 4
// speedup vs baseline: 2.0178x; 1.0378x over previous
#include <cuda_runtime.h>
#include <cuda_bf16.h>
#include <cstdint>
#include <math.h>

// ---------------- Problem constants ----------------
#define BB 2
#define LL 1024
#define DM 1024
#define DI 2048            // d_inner
#define DS 16              // d_state
#define DC 4               // d_conv
#define DR 64              // dt_rank
#define XZ_W (2*DI)        // 4096
#define XDBL_W (DR + 2*DS) // 96
#define MROWS (BB*LL)      // 2048

// ---------------- Scratch (device globals; no allocation allowed) ----------------
__device__ float g_xz  [MROWS*XZ_W];
__device__ float g_u   [MROWS*DI];
__device__ float g_xdbl[MROWS*XDBL_W];
__device__ float g_dt  [MROWS*DI];
__device__ __nv_bfloat16 g_xb   [MROWS*DM];
__device__ __nv_bfloat16 g_hb   [MROWS*DM];
__device__ __nv_bfloat16 g_ub   [MROWS*DI];
__device__ __nv_bfloat16 g_yb   [MROWS*DI];
__device__ __nv_bfloat16 g_xdblb[MROWS*XDBL_W];
__device__ __nv_bfloat16 g_Wib  [2*XZ_W*DM];
__device__ __nv_bfloat16 g_Wxb  [2*XDBL_W*DI];
__device__ __nv_bfloat16 g_Wdtb [2*DI*DR];
__device__ __nv_bfloat16 g_Wob  [2*DM*DI];

// ---------------- helpers ----------------
__device__ __forceinline__ uint32_t smem_u32(const void* p) {
    uint32_t a;
    asm("{ .reg .u64 t; cvta.to.shared.u64 t, %1; cvt.u32.u64 %0, t; }" : "=r"(a) : "l"(p));
    return a;
}
__device__ __forceinline__ void cp16(uint32_t s, const void* g) {
    asm volatile("cp.async.cg.shared.global [%0], [%1], 16;" :: "r"(s), "l"(g));
}
#define CP_COMMIT()  asm volatile("cp.async.commit_group;" ::: "memory")
#define CP_WAIT(n)   asm volatile("cp.async.wait_group %0;" :: "n"(n) : "memory")

__device__ __forceinline__ void ldsm4(uint32_t* r, uint32_t addr) {
    asm volatile("ldmatrix.sync.aligned.m8n8.x4.shared.b16 {%0,%1,%2,%3}, [%4];"
                 : "=r"(r[0]), "=r"(r[1]), "=r"(r[2]), "=r"(r[3]) : "r"(addr));
}
__device__ __forceinline__ void mma_bf16(float* c, const uint32_t* a, const uint32_t* b) {
    asm volatile(
        "mma.sync.aligned.m16n8k16.row.col.f32.bf16.bf16.f32 "
        "{%0,%1,%2,%3}, {%4,%5,%6,%7}, {%8,%9}, {%0,%1,%2,%3};"
        : "+f"(c[0]), "+f"(c[1]), "+f"(c[2]), "+f"(c[3])
        : "r"(a[0]), "r"(a[1]), "r"(a[2]), "r"(a[3]), "r"(b[0]), "r"(b[1]));
}

// ---------------- mma.sync bf16 NT GEMM ----------------
// C[m,n] = sum_k A[m*lda+k] * W[n*K+k]   (A, W bf16 K-major)
// CTA 128x128, BK=64, 3-stage cp.async, 8 warps: warp tile 32(M) x 64(N).
// SMEM tile rows are 128B (64 bf16) with 16B-chunk XOR swizzle (ch ^ (row&7)).
// EPI: 0=fp32, 1=softplus(c+bias[n]) fp32, 2=c+res fp32, 3=bf16 only, 4=fp32+bf16
#define STAGE 32768         // A 16KB + B 16KB
#define SMEM_GEMM (3*STAGE) // 98304
#define ELD 132             // epilogue fp32 row stride

template <int EPI>
__global__ void __launch_bounds__(256, 1)
gemm_mma(const __nv_bfloat16* __restrict__ A, int lda,
         const __nv_bfloat16* __restrict__ W,
         float* __restrict__ Cf, __nv_bfloat16* __restrict__ Cb,
         int N, int ldc, int K,
         const float* __restrict__ bias, const float* __restrict__ res)
{
    extern __shared__ __align__(16) char smem[];

    const int tid  = threadIdx.x;
    const int wid  = tid >> 5;
    const int lane = tid & 31;
    const int wm   = wid & 3;      // rows [wm*32, wm*32+32)
    const int wn   = wid >> 2;     // cols [wn*64, wn*64+64)
    const int bx   = blockIdx.x, by = blockIdx.y;
    const int bxN  = bx * 128;

    const uint32_t sbase = smem_u32(smem);
    const __nv_bfloat16* Ap = A + (size_t)(by * 128) * lda;
    const __nv_bfloat16* Wp = W + (size_t)bxN * K;

    const int nk = K >> 6;

    auto load_stage = [&](int kt) {
        const int st = kt % 3;
        const int k0 = kt * 64;
        uint32_t sa = sbase + st * STAGE;
        uint32_t sb = sa + 16384;
#pragma unroll
        for (int j = 0; j < 4; ++j) {
            int c = tid + 256 * j;          // 0..1023
            int row = c >> 3, ch = c & 7;
            uint32_t off = row * 128 + ((ch ^ (row & 7)) << 4);
            cp16(sa + off, Ap + (size_t)row * lda + k0 + ch * 8);
        }
#pragma unroll
        for (int j = 0; j < 4; ++j) {
            int c = tid + 256 * j;
            int row = c >> 3, ch = c & 7;
            uint32_t off = row * 128 + ((ch ^ (row & 7)) << 4);
            if (bxN + row < N)
                cp16(sb + off, Wp + (size_t)row * K + k0 + ch * 8);
        }
        CP_COMMIT();
    };

    float acc[2][8][4];
#pragma unroll
    for (int i = 0; i < 2; ++i)
#pragma unroll
        for (int j = 0; j < 8; ++j)
#pragma unroll
            for (int c = 0; c < 4; ++c) acc[i][j][c] = 0.f;

    // per-thread ldmatrix address components
    const int a_rl  = lane & 15;         // local row within 16
    const int a_kc  = lane >> 4;         // 0/1: k 16B-chunk within k-step
    const int a_xor = lane & 7;
    const int b_nl  = (lane & 7) + ((lane >> 4) << 3);  // 0..15 local n
    const int b_kc  = (lane >> 3) & 1;

    // prologue
    load_stage(0);
    if (nk > 1) load_stage(1); else CP_COMMIT();

    for (int kt = 0; kt < nk; ++kt) {
        CP_WAIT(1);
        __syncthreads();
        if (kt + 2 < nk) load_stage(kt + 2); else CP_COMMIT();

        const uint32_t sa = sbase + (kt % 3) * STAGE;
        const uint32_t sb = sa + 16384;
        const uint32_t aBase0 = sa + (wm * 32 + 0  + a_rl) * 128;
        const uint32_t aBase1 = sa + (wm * 32 + 16 + a_rl) * 128;

#pragma unroll
        for (int ks = 0; ks < 4; ++ks) {
            uint32_t af0[4], af1[4];
            uint32_t aoff = (uint32_t)(((ks * 2 + a_kc) ^ a_xor) << 4);
            ldsm4(af0, aBase0 + aoff);
            ldsm4(af1, aBase1 + aoff);
#pragma unroll
            for (int nj = 0; nj < 4; ++nj) {
                uint32_t bf[4];
                int nl = wn * 64 + nj * 16 + b_nl;
                uint32_t boff = nl * 128 + (((ks * 2 + b_kc) ^ (b_nl & 7)) << 4);
                ldsm4(bf, sb + boff);
                mma_bf16(acc[0][nj * 2 + 0], af0, bf + 0);
                mma_bf16(acc[0][nj * 2 + 1], af0, bf + 2);
                mma_bf16(acc[1][nj * 2 + 0], af1, bf + 0);
                mma_bf16(acc[1][nj * 2 + 1], af1, bf + 2);
            }
        }
        __syncthreads();
    }

    // ---------------- single-pass epilogue: acc -> SMEM fp32 -> coalesced GMEM ----------------
    float* sEpi = (float*)smem;   // [128][ELD] = 67584 B
#pragma unroll
    for (int mi = 0; mi < 2; ++mi)
#pragma unroll
        for (int nt = 0; nt < 8; ++nt) {
            int r  = wm * 32 + mi * 16 + (lane >> 2);
            int cc = wn * 64 + nt * 8 + (lane & 3) * 2;
            *(float2*)&sEpi[r * ELD + cc]       = make_float2(acc[mi][nt][0], acc[mi][nt][1]);
            *(float2*)&sEpi[(r + 8) * ELD + cc] = make_float2(acc[mi][nt][2], acc[mi][nt][3]);
        }
    __syncthreads();

    {
        int nn = tid & 127, r0 = tid >> 7;
        int n = bxN + nn;
        if (n < N) {
            float bv = (EPI == 1) ? bias[n] : 0.f;
#pragma unroll 4
            for (int rr = r0; rr < 128; rr += 2) {
                int m = by * 128 + rr;
                float v = sEpi[rr * ELD + nn];
                if (EPI == 1) {
                    float t = v + bv;
                    v = (t > 20.f) ? t : log1pf(__expf(t));
                    Cf[(size_t)m * ldc + n] = v;
                } else if (EPI == 2) {
                    Cf[(size_t)m * ldc + n] = v + res[(size_t)m * ldc + n];
                } else if (EPI == 3) {
                    Cb[(size_t)m * ldc + n] = __float2bfloat16(v);
                } else if (EPI == 4) {
                    Cf[(size_t)m * ldc + n] = v;
                    Cb[(size_t)m * ldc + n] = __float2bfloat16(v);
                } else {
                    Cf[(size_t)m * ldc + n] = v;
                }
            }
        }
    }
}

// ---------------- fp32 -> bf16 convert ----------------
__global__ void cvt_kernel(const float* __restrict__ in, __nv_bfloat16* __restrict__ out, int n)
{
    int i = (blockIdx.x * blockDim.x + threadIdx.x) * 8;
    if (i + 7 < n) {
        float4 v0 = *(const float4*)(in + i);
        float4 v1 = *(const float4*)(in + i + 4);
        __nv_bfloat162 b0 = __floats2bfloat162_rn(v0.x, v0.y);
        __nv_bfloat162 b1 = __floats2bfloat162_rn(v0.z, v0.w);
        __nv_bfloat162 b2 = __floats2bfloat162_rn(v1.x, v1.y);
        __nv_bfloat162 b3 = __floats2bfloat162_rn(v1.z, v1.w);
        uint4 o;
        o.x = *(uint32_t*)&b0; o.y = *(uint32_t*)&b1;
        o.z = *(uint32_t*)&b2; o.w = *(uint32_t*)&b3;
        *(uint4*)(out + i) = o;
    }
}

// ---------------- Depthwise causal conv1d (width 4) + bias + SiLU ----------------
__global__ void conv_silu_kernel(const float* __restrict__ xz,
                                 const float* __restrict__ cw,
                                 const float* __restrict__ cb,
                                 float* __restrict__ u,
                                 __nv_bfloat16* __restrict__ ub)
{
    int idx = blockIdx.x * blockDim.x + threadIdx.x;
    if (idx >= BB * LL * DI) return;
    int d  = idx & (DI - 1);
    int bl = idx >> 11;
    int l  = bl & (LL - 1);
    int b  = bl >> 10;

    float w0 = cw[d * 4 + 0], w1 = cw[d * 4 + 1];
    float w2 = cw[d * 4 + 2], w3 = cw[d * 4 + 3];
    float acc = cb[d];
    const float* base = xz + ((size_t)b * LL) * XZ_W + d;
    if (l - 3 >= 0) acc += base[(size_t)(l - 3) * XZ_W] * w0;
    if (l - 2 >= 0) acc += base[(size_t)(l - 2) * XZ_W] * w1;
    if (l - 1 >= 0) acc += base[(size_t)(l - 1) * XZ_W] * w2;
    acc += base[(size_t)l * XZ_W] * w3;
    float s = acc / (1.f + __expf(-acc));
    u[idx]  = s;
    ub[idx] = __float2bfloat16(s);
}

// ---------------- Selective scan ----------------
#define TCH 64
__global__ void scan_kernel(const float* __restrict__ dt,
                            const float* __restrict__ u,
                            const float* __restrict__ xdbl,
                            const float* __restrict__ A_log,
                            const float* __restrict__ Dvec,
                            const float* __restrict__ xz,
                            __nv_bfloat16* __restrict__ yb)
{
    __shared__ float sB[TCH][DS];
    __shared__ float sC[TCH][DS];

    const int q  = threadIdx.x & 3;
    const int dl = threadIdx.x >> 2;
    const int b  = blockIdx.x >> 6;
    const int d  = ((blockIdx.x & 63) << 5) + dl;

    float Av[4];
#pragma unroll
    for (int i = 0; i < 4; ++i)
        Av[i] = -__expf(A_log[(size_t)d * DS + q * 4 + i]);
    const float Dv = Dvec[d];

    float h0 = 0.f, h1 = 0.f, h2 = 0.f, h3 = 0.f;

    for (int t0 = 0; t0 < LL; t0 += TCH) {
        __syncthreads();
        for (int i = threadIdx.x; i < TCH * DS; i += blockDim.x) {
            int tt = i >> 4, n = i & 15;
            size_t row = ((size_t)b * LL + t0 + tt) * XDBL_W;
            sB[tt][n] = xdbl[row + DR + n];
            sC[tt][n] = xdbl[row + DR + DS + n];
        }
        __syncthreads();

#pragma unroll 4
        for (int tt = 0; tt < TCH; ++tt) {
            int t = t0 + tt;
            size_t off = ((size_t)b * LL + t) * DI + d;
            float dtv = dt[off];
            float uv  = u[off];
            float dtu = dtv * uv;

            float dA0 = __expf(dtv * Av[0]);
            float dA1 = __expf(dtv * Av[1]);
            float dA2 = __expf(dtv * Av[2]);
            float dA3 = __expf(dtv * Av[3]);
            h0 = dA0 * h0 + dtu * sB[tt][q * 4 + 0];
            h1 = dA1 * h1 + dtu * sB[tt][q * 4 + 1];
            h2 = dA2 * h2 + dtu * sB[tt][q * 4 + 2];
            h3 = dA3 * h3 + dtu * sB[tt][q * 4 + 3];
            float ys = h0 * sC[tt][q * 4 + 0] + h1 * sC[tt][q * 4 + 1]
                     + h2 * sC[tt][q * 4 + 2] + h3 * sC[tt][q * 4 + 3];

            ys += __shfl_xor_sync(0xffffffff, ys, 1);
            ys += __shfl_xor_sync(0xffffffff, ys, 2);

            if (q == 0) {
                float zv = xz[((size_t)b * LL + t) * XZ_W + DI + d];
                float sz = zv / (1.f + __expf(-zv));
                yb[off] = __float2bfloat16((ys + uv * Dv) * sz);
            }
        }
    }
}

// ---------------- Host launcher ----------------
extern "C" void kernel_launch(void* const* d_in, const int* in_sizes, int n_in,
                              void* d_out, int out_size)
{
    const float* x      = (const float*)d_in[0];
    const float* W_in   = (const float*)d_in[1];
    const float* conv_w = (const float*)d_in[2];
    const float* conv_b = (const float*)d_in[3];
    const float* W_x    = (const float*)d_in[4];
    const float* W_dt   = (const float*)d_in[5];
    const float* b_dt   = (const float*)d_in[6];
    const float* A_log  = (const float*)d_in[7];
    const float* Dvec   = (const float*)d_in[8];
    const float* W_out  = (const float*)d_in[9];
    float* out = (float*)d_out;

    float *xz, *u, *xdbl, *dt;
    __nv_bfloat16 *xb, *hb, *ub, *yb, *xdblb, *Wib, *Wxb, *Wdtb, *Wob;
    cudaGetSymbolAddress((void**)&xz,    g_xz);
    cudaGetSymbolAddress((void**)&u,     g_u);
    cudaGetSymbolAddress((void**)&xdbl,  g_xdbl);
    cudaGetSymbolAddress((void**)&dt,    g_dt);
    cudaGetSymbolAddress((void**)&xb,    g_xb);
    cudaGetSymbolAddress((void**)&hb,    g_hb);
    cudaGetSymbolAddress((void**)&ub,    g_ub);
    cudaGetSymbolAddress((void**)&yb,    g_yb);
    cudaGetSymbolAddress((void**)&xdblb, g_xdblb);
    cudaGetSymbolAddress((void**)&Wib,   g_Wib);
    cudaGetSymbolAddress((void**)&Wxb,   g_Wxb);
    cudaGetSymbolAddress((void**)&Wdtb,  g_Wdtb);
    cudaGetSymbolAddress((void**)&Wob,   g_Wob);

    cudaFuncSetAttribute(gemm_mma<0>, cudaFuncAttributeMaxDynamicSharedMemorySize, SMEM_GEMM);
    cudaFuncSetAttribute(gemm_mma<1>, cudaFuncAttributeMaxDynamicSharedMemorySize, SMEM_GEMM);
    cudaFuncSetAttribute(gemm_mma<2>, cudaFuncAttributeMaxDynamicSharedMemorySize, SMEM_GEMM);
    cudaFuncSetAttribute(gemm_mma<3>, cudaFuncAttributeMaxDynamicSharedMemorySize, SMEM_GEMM);
    cudaFuncSetAttribute(gemm_mma<4>, cudaFuncAttributeMaxDynamicSharedMemorySize, SMEM_GEMM);

    auto cvt = [&](const float* src, __nv_bfloat16* dst, int n) {
        cvt_kernel<<<(n / 8 + 255) / 256, 256>>>(src, dst, n);
    };
    cvt(x,     xb,   MROWS * DM);
    cvt(W_in,  Wib,  2 * XZ_W * DM);
    cvt(W_x,   Wxb,  2 * XDBL_W * DI);
    cvt(W_dt,  Wdtb, 2 * DI * DR);
    cvt(W_out, Wob,  2 * DM * DI);

    for (int layer = 0; layer < 2; ++layer) {
        const __nv_bfloat16* in_b   = (layer == 0) ? xb : hb;
        const __nv_bfloat16* Wib_l  = Wib  + (size_t)layer * XZ_W * DM;
        const __nv_bfloat16* Wxb_l  = Wxb  + (size_t)layer * XDBL_W * DI;
        const __nv_bfloat16* Wdtb_l = Wdtb + (size_t)layer * DI * DR;
        const __nv_bfloat16* Wob_l  = Wob  + (size_t)layer * DM * DI;
        const float* conv_w_l = conv_w + (size_t)layer * DI * DC;
        const float* conv_b_l = conv_b + (size_t)layer * DI;
        const float* b_dt_l   = b_dt   + (size_t)layer * DI;
        const float* A_log_l  = A_log  + (size_t)layer * DI * DS;
        const float* D_l      = Dvec   + (size_t)layer * DI;

        // 1) xz = in @ W_in^T : M=2048, N=4096, K=1024
        gemm_mma<0><<<dim3(XZ_W / 128, MROWS / 128), 256, SMEM_GEMM>>>(
            in_b, DM, Wib_l, xz, nullptr, XZ_W, XZ_W, DM, nullptr, nullptr);

        // 2) u = silu(causal_conv(xz[:, :DI]))
        conv_silu_kernel<<<(BB * LL * DI) / 256, 256>>>(xz, conv_w_l, conv_b_l, u, ub);

        // 3) x_dbl = u @ W_x^T : N=96, K=2048
        gemm_mma<4><<<dim3(1, MROWS / 128), 256, SMEM_GEMM>>>(
            ub, DI, Wxb_l, xdbl, xdblb, XDBL_W, XDBL_W, DI, nullptr, nullptr);

        // 4) dt = softplus(x_dbl[:, :64] @ W_dt^T + b_dt) : N=2048, K=64
        gemm_mma<1><<<dim3(DI / 128, MROWS / 128), 256, SMEM_GEMM>>>(
            xdblb, XDBL_W, Wdtb_l, dt, nullptr, DI, DI, DR, b_dt_l, nullptr);

        // 5) selective scan
        scan_kernel<<<BB * (DI / 32), 128>>>(dt, u, xdbl, A_log_l, D_l, xz, yb);

        // 6) out = y @ W_out^T : N=1024, K=2048
        if (layer == 0) {
            gemm_mma<3><<<dim3(DM / 128, MROWS / 128), 256, SMEM_GEMM>>>(
                yb, DI, Wob_l, nullptr, hb, DM, DM, DI, nullptr, nullptr);
        } else {
            gemm_mma<2><<<dim3(DM / 128, MROWS / 128), 256, SMEM_GEMM>>>(
                yb, DI, Wob_l, out, nullptr, DM, DM, DI, nullptr, x);
        }
    }
}